// round 5
// baseline (speedup 1.0000x reference)
#include <cuda_runtime.h>

#define HH 480
#define WW 640
#define NC 3
#define SKIP 5
#define PH 96            // HH/SKIP
#define PW 128           // WW/SKIP
#define NP (PH*PW)       // 12288 sampled pixels
#define BH 60            // bin rows   (GRID=8, start 4)
#define BWID 80          // bin cols
#define NB (BH*BWID)     // 4800 bins
#define BPT 4            // bins per thread (same bin row)
#define CPG (BWID/BPT)   // 20 col-groups per bin row
#define NTH (BH*CPG)     // 1200 worker threads (bin side)
#define BGRID 5          // 5*256 = 1280 threads >= 1200
#define PSPLIT 118       // pixel-slice CTAs -> 5*118 = 590 CTAs (~4/SM)
#define TOTAL_CTAS (BGRID*PSPLIT)

// ---------- device scratch (zero-initialized at module load) ----------
__device__ float g_px[2*NP];   // NEGATED px
__device__ float g_py[2*NP];   // NEGATED py
__device__ float g_ux[2*NP];   // 2*ux
__device__ float g_uy[2*NP];   // 2*uy
__device__ float g_dd[2*NP];   // dist
__device__ int   g_n[2];       // compacted counts (class 1,2) -- reset by epilogue
__device__ int   g_cnt[NC];    // raw label counts             -- reset by epilogue
__device__ int   g_done;       // CTA completion counter       -- reset by epilogue
__device__ float g_rois_scratch[NC*6];
__device__ float g_hough_scratch[NC*NB];

// ---------- kernel 1: zero hough + gather/compact sampled pixels ----------
#define PREP_TH (NC*NB)   // 14400 >= NP
__global__ void prep_k(const int* __restrict__ label,
                       const float* __restrict__ vert,
                       float* __restrict__ hough) {
    int i = blockIdx.x * blockDim.x + threadIdx.x;
    if (i < NC*NB) hough[i] = 0.0f;

    if (i >= NP) return;
    int r = i / PW, c = i % PW;
    int vy = r * SKIP, vx = c * SKIP;
    int vl = label[vy * WW + vx];
    atomicAdd(&g_cnt[vl], 1);
    if (vl > 0) {
        int seg  = vl - 1;
        int slot = atomicAdd(&g_n[seg], 1) + seg * NP;
        int base = (vl * 3) * (HH * WW) + vy * WW + vx;
        g_px[slot] = -(float)vx;
        g_py[slot] = -(float)vy;
        g_ux[slot] = 2.0f * vert[base];
        g_uy[slot] = 2.0f * vert[base + HH * WW];
        g_dd[slot] = vert[base + 2 * HH * WW];
    }
}

// inlier test: dot>0 && dot^2>nxy  <=>  bits(dot*|dot|) > bits(nxy), nxy>0
__device__ __forceinline__ int inlier(float ddx, float ddy_t2, float dyu,
                                      float ux2, float nxy_in) {
    // (unused helper placeholder; logic kept inline in loops)
    return 0;
}

// ---------- kernel 2: vote counting + fused epilogue ----------
__global__ void __launch_bounds__(256, 4)
vote_k(float* __restrict__ hough,
       float* __restrict__ rois,
       const float* __restrict__ meta,
       const float* __restrict__ extents) {
    __shared__ float s_px[256], s_py[256], s_ux[256], s_uy[256];
    __shared__ float sv[256];
    __shared__ int   si[256];
    __shared__ int   s_last;

    int tid = threadIdx.x;
    int gt  = blockIdx.x * 256 + tid;
    bool active = gt < NTH;
    int binrow = gt / CPG;
    int colg   = gt % CPG;
    float byf  = 4.0f + 8.0f * (float)binrow;
    float bxv[BPT];
    #pragma unroll
    for (int b = 0; b < BPT; b++) bxv[b] = 4.0f + 8.0f * (float)(colg * BPT + b);

    for (int seg = 0; seg < 2; seg++) {
        int n     = g_n[seg];
        int chunk = (n + PSPLIT - 1) / PSPLIT;
        int start = blockIdx.y * chunk;
        int end   = min(start + chunk, n);

        int cH[BPT] = {0, 0, 0, 0};

        for (int t = start; t < end; t += 256) {
            int m = min(256, end - t);
            __syncthreads();
            if (tid < m) {
                int s = seg * NP + t + tid;
                s_px[tid] = g_px[s];
                s_py[tid] = g_py[s];
                s_ux[tid] = g_ux[s];
                s_uy[tid] = g_uy[s];
            }
            __syncthreads();

            #pragma unroll 4
            for (int j = 0; j < m; j++) {
                float npx = s_px[j], npy = s_py[j];   // negated coords
                float ux2 = s_ux[j], uy2 = s_uy[j];   // 2*ux, 2*uy
                float ddy = byf + npy;
                float t2  = fmaf(ddy, ddy, 1e-6f);    // ddy^2 + eps
                float dyu = ddy * uy2;                // ddy * 2uy
                #pragma unroll
                for (int b = 0; b < BPT; b++) {
                    float ddx = bxv[b] + npx;
                    float nxy = fmaf(ddx, ddx, t2);   // >0 always
                    float dot = fmaf(ddx, ux2, dyu);  // 2*(ddx*ux+ddy*uy)
                    float da  = dot * fabsf(dot);     // signed square
                    cH[b] += (__float_as_int(da) > __float_as_int(nxy));
                }
            }
        }

        if (active) {
            int binbase = binrow * BWID + colg * BPT;
            #pragma unroll
            for (int b = 0; b < BPT; b++) {
                if (cH[b] != 0)
                    atomicAdd(&hough[(seg + 1) * NB + binbase + b], (float)cH[b]);
            }
        }
        __syncthreads();
    }

    // ---------- fused epilogue: last CTA ----------
    __threadfence();
    __syncthreads();
    if (tid == 0) {
        int t = atomicAdd(&g_done, 1);
        s_last = (t == TOTAL_CTAS - 1);
    }
    __syncthreads();
    if (!s_last) return;
    __threadfence();   // acquire: all CTAs' atomics visible

    for (int c = 0; c < NC; c++) {
        int peak = 0; float votes = 0.0f; float ds = 0.0f;
        if (c > 0) {
            // --- argmax over hough row c (first max on ties) ---
            float best = -1.0f; int bi = 0;
            #pragma unroll
            for (int k = 0; k < 19; k++) {
                int i = tid + k * 256;
                float v = (i < NB) ? __ldcg(&hough[c * NB + i]) : -2.0f;
                if (v > best) { best = v; bi = i; }
            }
            sv[tid] = best; si[tid] = bi;
            __syncthreads();
            #pragma unroll
            for (int s = 128; s > 0; s >>= 1) {
                if (tid < s) {
                    float v2 = sv[tid + s]; int i2 = si[tid + s];
                    if (v2 > sv[tid] || (v2 == sv[tid] && i2 < si[tid])) {
                        sv[tid] = v2; si[tid] = i2;
                    }
                }
                __syncthreads();
            }
            peak = si[0]; votes = sv[0];

            // --- dsum at the peak bin only ---
            float pbx = 4.0f + 8.0f * (float)(peak % BWID);
            float pby = 4.0f + 8.0f * (float)(peak / BWID);
            int   seg = c - 1;
            int   n   = g_n[seg];
            float acc = 0.0f;
            for (int t = tid; t < n; t += 256) {
                int s = seg * NP + t;
                float npx = g_px[s], npy = g_py[s];
                float ux2 = g_ux[s], uy2 = g_uy[s];
                float ddy = pby + npy;
                float t2  = fmaf(ddy, ddy, 1e-6f);
                float dyu = ddy * uy2;
                float ddx = pbx + npx;
                float nxy = fmaf(ddx, ddx, t2);
                float dot = fmaf(ddx, ux2, dyu);
                float da  = dot * fabsf(dot);
                if (__float_as_int(da) > __float_as_int(nxy)) acc += g_dd[s];
            }
            sv[tid] = acc;
            __syncthreads();
            #pragma unroll
            for (int s = 128; s > 0; s >>= 1) {
                if (tid < s) sv[tid] += sv[tid + s];
                __syncthreads();
            }
            ds = sv[0];
            __syncthreads();
        }

        if (tid == 0) {
            float depth = ds / fmaxf(votes, 1.0f);
            float cx = 4.0f + 8.0f * (float)(peak % BWID);
            float cy = 4.0f + 8.0f * (float)(peak / BWID);
            float cnt = (float)g_cnt[c];
            float score = votes / fmaxf(cnt, 1.0f);
            bool  valid = (cnt > 5.0f) && (score > 0.3f);
            float fx = meta[0], fy = meta[4];
            float e0 = extents[c*3+0], e1 = extents[c*3+1], e2 = extents[c*3+2];
            float diag = sqrtf(e0*e0 + e1*e1 + e2*e2);
            float sz = fmaxf(fabsf(depth), 0.001f);
            float bw = fabsf(diag * fx) / sz;
            float bh = fabsf(diag * fy) / sz;
            rois[c*6+0] = (float)c;
            rois[c*6+1] = cx - bw * 0.5f;
            rois[c*6+2] = cy - bh * 0.5f;
            rois[c*6+3] = cx + bw * 0.5f;
            rois[c*6+4] = cy + bh * 0.5f;
            rois[c*6+5] = valid ? score : 0.0f;
        }
        __syncthreads();
    }

    // reset counters for the next graph replay
    if (tid < 2)  g_n[tid] = 0;
    if (tid < NC) g_cnt[tid] = 0;
    if (tid == 0) g_done = 0;
}

extern "C" void kernel_launch(void* const* d_in, const int* in_sizes, int n_in,
                              void* d_out, int out_size) {
    const int*   label = (const int*)  d_in[0];
    const float* vert  = (const float*)d_in[1];
    const float* meta  = (const float*)d_in[2];
    const float* ext   = (const float*)d_in[3];
    float* out = (float*)d_out;

    // Output is the flattened tuple (rois[3,6], hough[3,4800]) -> 18 + 14400.
    float *rois_p, *hough_p;
    if (out_size >= NC*6 + NC*NB) {
        rois_p = out; hough_p = out + NC*6;
    } else if (out_size >= NC*NB) {
        void* tmp = nullptr;
        cudaGetSymbolAddress(&tmp, g_rois_scratch);
        rois_p = (float*)tmp; hough_p = out;
    } else {
        void* tmp = nullptr;
        cudaGetSymbolAddress(&tmp, g_hough_scratch);
        rois_p = out; hough_p = (float*)tmp;
    }

    prep_k<<<(PREP_TH + 255) / 256, 256>>>(label, vert, hough_p);
    dim3 vgrid(BGRID, PSPLIT);
    vote_k<<<vgrid, 256>>>(hough_p, rois_p, meta, ext);
}

// round 6
// speedup vs baseline: 1.0643x; 1.0643x over previous
#include <cuda_runtime.h>

#define HH 480
#define WW 640
#define NC 3
#define SKIP 5
#define PH 96            // HH/SKIP
#define PW 128           // WW/SKIP
#define NP (PH*PW)       // 12288 sampled pixels
#define BH 60            // bin rows   (GRID=8, start 4)
#define BWID 80          // bin cols
#define NB (BH*BWID)     // 4800 bins
#define BPT 4            // bins per thread (same bin row)  -- R1/R3 proven config
#define CPG (BWID/BPT)   // 20 col-groups per bin row
#define NTH (BH*CPG)     // 1200 worker threads (bin side)
#define BGRID 5          // 5*256 = 1280 threads >= 1200
#define PSPLIT 59        // pixel-slice CTAs -> 5*59 = 295 CTAs (~2/SM)
#define TOTAL_CTAS (BGRID*PSPLIT)

// ---------- device scratch (zero-initialized at module load) ----------
__device__ float g_px[2*NP];
__device__ float g_py[2*NP];
__device__ float g_ux[2*NP];   // 2*ux
__device__ float g_uy[2*NP];   // 2*uy
__device__ float g_dd[2*NP];   // dist
__device__ int   g_n[2];       // compacted counts (class 1,2) -- reset by epilogue
__device__ int   g_cnt[NC];    // raw label counts             -- reset by epilogue
__device__ int   g_done;       // CTA completion counter       -- reset by epilogue
__device__ float g_dsum[2*NB];
__device__ float g_rois_scratch[NC*6];
__device__ float g_hough_scratch[NC*NB];

// ---------- kernel 1: zero hough/dsum + gather/compact sampled pixels ----------
#define PREP_TH (NC*NB)   // 14400 >= NP
__global__ void prep_k(const int* __restrict__ label,
                       const float* __restrict__ vert,
                       float* __restrict__ hough) {
    int i = blockIdx.x * blockDim.x + threadIdx.x;
    if (i < NC*NB) hough[i] = 0.0f;
    if (i < 2*NB)  g_dsum[i] = 0.0f;

    if (i >= NP) return;
    int r = i / PW, c = i % PW;
    int vy = r * SKIP, vx = c * SKIP;
    int vl = label[vy * WW + vx];
    atomicAdd(&g_cnt[vl], 1);
    if (vl > 0) {
        int seg  = vl - 1;
        int slot = atomicAdd(&g_n[seg], 1) + seg * NP;
        int base = (vl * 3) * (HH * WW) + vy * WW + vx;
        g_px[slot] = (float)vx;
        g_py[slot] = (float)vy;
        g_ux[slot] = 2.0f * vert[base];
        g_uy[slot] = 2.0f * vert[base + HH * WW];
        g_dd[slot] = vert[base + 2 * HH * WW];
    }
}

// ---------- kernel 2: pairwise voting (R3 mainloop verbatim) + fused epilogue ----------
__global__ void __launch_bounds__(256, 2)
vote_k(float* __restrict__ hough,
       float* __restrict__ rois,
       const float* __restrict__ meta,
       const float* __restrict__ extents) {
    __shared__ float s_px[256], s_py[256], s_ux[256], s_uy[256], s_dd[256];
    __shared__ float sv[256];
    __shared__ int   si[256];
    __shared__ int   s_last;

    int tid = threadIdx.x;
    int gt  = blockIdx.x * 256 + tid;
    bool active = gt < NTH;
    int binrow = gt / CPG;
    int colg   = gt % CPG;
    float byf  = 4.0f + 8.0f * (float)binrow;
    float bx0  = 4.0f + 8.0f * (float)(colg * BPT);

    for (int seg = 0; seg < 2; seg++) {
        int n     = g_n[seg];
        int chunk = (n + PSPLIT - 1) / PSPLIT;
        int start = blockIdx.y * chunk;
        int end   = min(start + chunk, n);

        float aH[BPT] = {0.f, 0.f, 0.f, 0.f};
        float aD[BPT] = {0.f, 0.f, 0.f, 0.f};

        for (int t = start; t < end; t += 256) {
            int m = min(256, end - t);
            __syncthreads();
            if (tid < m) {
                int s = seg * NP + t + tid;
                s_px[tid] = g_px[s];
                s_py[tid] = g_py[s];
                s_ux[tid] = g_ux[s];
                s_uy[tid] = g_uy[s];
                s_dd[tid] = g_dd[s];
            }
            __syncthreads();

            #pragma unroll 4
            for (int j = 0; j < m; j++) {
                float px = s_px[j], py = s_py[j];
                float ux = s_ux[j], uy = s_uy[j];
                float dd = s_dd[j];
                float ddy = byf - py;
                float t2  = fmaf(ddy, ddy, 1e-6f);   // ddy^2 + eps
                float dyu = ddy * uy;                // ddy * 2uy
                #pragma unroll
                for (int b = 0; b < BPT; b++) {
                    float ddx = (bx0 + 8.0f * (float)b) - px;
                    float nxy = fmaf(ddx, ddx, t2);   // ddx^2+ddy^2+eps
                    float dot = fmaf(ddx, ux, dyu);   // 2*(ddx*ux+ddy*uy)
                    bool  ok  = (dot > 0.0f) && (dot * dot > nxy);
                    aH[b] += ok ? 1.0f : 0.0f;
                    aD[b] += ok ? dd   : 0.0f;
                }
            }
        }

        if (active) {
            int binbase = binrow * BWID + colg * BPT;
            #pragma unroll
            for (int b = 0; b < BPT; b++) {
                if (aH[b] != 0.0f) {
                    atomicAdd(&hough[(seg + 1) * NB + binbase + b], aH[b]);
                    atomicAdd(&g_dsum[seg * NB + binbase + b], aD[b]);
                }
            }
        }
        __syncthreads();
    }

    // ---------- fused epilogue: last CTA does argmax + ROI math ----------
    __threadfence();
    __syncthreads();
    if (tid == 0) {
        int t = atomicAdd(&g_done, 1);
        s_last = (t == TOTAL_CTAS - 1);
    }
    __syncthreads();
    if (!s_last) return;
    __threadfence();   // acquire: all other CTAs' atomics visible via L2

    for (int c = 0; c < NC; c++) {
        int peak; float votes;
        if (c == 0) {            // class-0 hough row is identically zero
            peak = 0; votes = 0.0f;
        } else {
            float best = -1.0f; int bi = 0;
            #pragma unroll
            for (int k = 0; k < 19; k++) {
                int i = tid + k * 256;
                float v = (i < NB) ? __ldcg(&hough[c * NB + i]) : -2.0f;
                if (v > best) { best = v; bi = i; }   // ascending i -> first max
            }
            sv[tid] = best; si[tid] = bi;
            __syncthreads();
            #pragma unroll
            for (int s = 128; s > 0; s >>= 1) {
                if (tid < s) {
                    float v2 = sv[tid + s]; int i2 = si[tid + s];
                    if (v2 > sv[tid] || (v2 == sv[tid] && i2 < si[tid])) {
                        sv[tid] = v2; si[tid] = i2;
                    }
                }
                __syncthreads();
            }
            peak = si[0]; votes = sv[0];
            __syncthreads();
        }

        if (tid == 0) {
            float ds    = (c > 0) ? __ldcg(&g_dsum[(c - 1) * NB + peak]) : 0.0f;
            float depth = ds / fmaxf(votes, 1.0f);
            float cx = 4.0f + 8.0f * (float)(peak % BWID);
            float cy = 4.0f + 8.0f * (float)(peak / BWID);
            float cnt = (float)g_cnt[c];
            float score = votes / fmaxf(cnt, 1.0f);
            bool  valid = (cnt > 5.0f) && (score > 0.3f);
            float fx = meta[0], fy = meta[4];
            float e0 = extents[c*3+0], e1 = extents[c*3+1], e2 = extents[c*3+2];
            float diag = sqrtf(e0*e0 + e1*e1 + e2*e2);
            float sz = fmaxf(fabsf(depth), 0.001f);
            float bw = fabsf(diag * fx) / sz;
            float bh = fabsf(diag * fy) / sz;
            rois[c*6+0] = (float)c;
            rois[c*6+1] = cx - bw * 0.5f;
            rois[c*6+2] = cy - bh * 0.5f;
            rois[c*6+3] = cx + bw * 0.5f;
            rois[c*6+4] = cy + bh * 0.5f;
            rois[c*6+5] = valid ? score : 0.0f;
        }
        __syncthreads();
    }

    // reset counters for the next graph replay
    if (tid < 2)  g_n[tid] = 0;
    if (tid < NC) g_cnt[tid] = 0;
    if (tid == 0) g_done = 0;
}

extern "C" void kernel_launch(void* const* d_in, const int* in_sizes, int n_in,
                              void* d_out, int out_size) {
    const int*   label = (const int*)  d_in[0];
    const float* vert  = (const float*)d_in[1];
    const float* meta  = (const float*)d_in[2];
    const float* ext   = (const float*)d_in[3];
    float* out = (float*)d_out;

    // Output is the flattened tuple (rois[3,6], hough[3,4800]) -> 18 + 14400.
    float *rois_p, *hough_p;
    if (out_size >= NC*6 + NC*NB) {
        rois_p = out; hough_p = out + NC*6;
    } else if (out_size >= NC*NB) {
        void* tmp = nullptr;
        cudaGetSymbolAddress(&tmp, g_rois_scratch);
        rois_p = (float*)tmp; hough_p = out;
    } else {
        void* tmp = nullptr;
        cudaGetSymbolAddress(&tmp, g_hough_scratch);
        rois_p = out; hough_p = (float*)tmp;
    }

    prep_k<<<(PREP_TH + 255) / 256, 256>>>(label, vert, hough_p);
    dim3 vgrid(BGRID, PSPLIT);
    vote_k<<<vgrid, 256>>>(hough_p, rois_p, meta, ext);
}

// round 7
// speedup vs baseline: 1.1941x; 1.1220x over previous
#include <cuda_runtime.h>

#define HH 480
#define WW 640
#define NC 3
#define SKIP 5
#define PH 96            // HH/SKIP
#define PW 128           // WW/SKIP
#define NP (PH*PW)       // 12288 sampled pixels
#define BH 60            // bin rows   (GRID=8, start 4)
#define BWID 80          // bin cols
#define NB (BH*BWID)     // 4800 bins
#define BPT 4            // bins per thread (same bin row)  -- proven config
#define CPG (BWID/BPT)   // 20 col-groups per bin row
#define NTH (BH*CPG)     // 1200 worker threads (bin side)
#define BGRID 5          // 5*256 = 1280 threads >= 1200
#define PSPLIT 59        // pixel-slice CTAs -> 5*59 = 295 CTAs (~2/SM)

// ---------- device scratch (zero-initialized at module load) ----------
__device__ float4 g_pix[2*NP]; // {px, py, 2ux, 2uy}
__device__ float  g_dd[2*NP];  // dist
__device__ int    g_n[2];      // compacted counts (class 1,2)
__device__ int    g_cnt[NC];   // raw label counts (incl. class 0)
__device__ float  g_dsum[2*NB];
__device__ float  g_rois_scratch[NC*6];
__device__ float  g_hough_scratch[NC*NB];

// ---------- kernel 0: zero small counters ----------
__global__ void zero_small_k() {
    int i = threadIdx.x;
    if (i < 2)  g_n[i] = 0;
    if (i < NC) g_cnt[i] = 0;
}

// ---------- kernel 1: zero hough/dsum + gather/compact/prune sampled pixels ----------
#define PREP_TH (NC*NB)   // 14400 >= NP
__global__ void prep_k(const int* __restrict__ label,
                       const float* __restrict__ vert,
                       float* __restrict__ hough) {
    int i = blockIdx.x * blockDim.x + threadIdx.x;
    if (i < NC*NB) hough[i] = 0.0f;
    if (i < 2*NB)  g_dsum[i] = 0.0f;

    if (i >= NP) return;
    int r = i / PW, c = i % PW;
    int vy = r * SKIP, vx = c * SKIP;
    int vl = label[vy * WW + vx];
    atomicAdd(&g_cnt[vl], 1);
    if (vl > 0) {
        int base = (vl * 3) * (HH * WW) + vy * WW + vx;
        float ux = vert[base];
        float uy = vert[base + HH * WW];
        // prune: cos = (d.u)/|d| <= |u|; if ux^2+uy^2 <= 0.25, cos>0.5 impossible.
        // Such pixels contribute 0 to hough and dsum (counts handled above).
        if (fmaf(ux, ux, uy * uy) > 0.25f) {
            int seg  = vl - 1;
            int slot = atomicAdd(&g_n[seg], 1) + seg * NP;
            g_pix[slot] = make_float4((float)vx, (float)vy, 2.0f * ux, 2.0f * uy);
            g_dd[slot]  = vert[base + 2 * HH * WW];
        }
    }
}

// ---------- kernel 2: pairwise voting (R3 mainloop, float4 pixel record) ----------
__global__ void __launch_bounds__(256, 2)
vote_k(float* __restrict__ hough) {
    __shared__ float4 s_pix[256];
    __shared__ float  s_dd[256];

    int tid = threadIdx.x;
    int gt  = blockIdx.x * 256 + tid;
    bool active = gt < NTH;
    int binrow = gt / CPG;
    int colg   = gt % CPG;
    float byf  = 4.0f + 8.0f * (float)binrow;
    float bx0  = 4.0f + 8.0f * (float)(colg * BPT);

    for (int seg = 0; seg < 2; seg++) {
        int n     = g_n[seg];
        int chunk = (n + PSPLIT - 1) / PSPLIT;
        int start = blockIdx.y * chunk;
        int end   = min(start + chunk, n);

        float aH[BPT] = {0.f, 0.f, 0.f, 0.f};
        float aD[BPT] = {0.f, 0.f, 0.f, 0.f};

        for (int t = start; t < end; t += 256) {
            int m = min(256, end - t);
            __syncthreads();
            if (tid < m) {
                int s = seg * NP + t + tid;
                s_pix[tid] = g_pix[s];
                s_dd[tid]  = g_dd[s];
            }
            __syncthreads();

            #pragma unroll 4
            for (int j = 0; j < m; j++) {
                float4 P = s_pix[j];                 // one LDS.128 (broadcast)
                float dd = s_dd[j];
                float px = P.x, py = P.y, ux = P.z, uy = P.w;
                float ddy = byf - py;
                float t2  = fmaf(ddy, ddy, 1e-6f);   // ddy^2 + eps
                float dyu = ddy * uy;                // ddy * 2uy
                #pragma unroll
                for (int b = 0; b < BPT; b++) {
                    float ddx = (bx0 + 8.0f * (float)b) - px;
                    float nxy = fmaf(ddx, ddx, t2);   // ddx^2+ddy^2+eps
                    float dot = fmaf(ddx, ux, dyu);   // 2*(ddx*ux+ddy*uy)
                    bool  ok  = (dot > 0.0f) && (dot * dot > nxy);
                    aH[b] += ok ? 1.0f : 0.0f;
                    aD[b] += ok ? dd   : 0.0f;
                }
            }
        }

        if (active) {
            int binbase = binrow * BWID + colg * BPT;
            #pragma unroll
            for (int b = 0; b < BPT; b++) {
                if (aH[b] != 0.0f) {
                    atomicAdd(&hough[(seg + 1) * NB + binbase + b], aH[b]);
                    atomicAdd(&g_dsum[seg * NB + binbase + b], aD[b]);
                }
            }
        }
        __syncthreads();
    }
}

// ---------- kernel 3: argmax + ROI epilogue (3 CTAs, one per class) ----------
__global__ void finish_k(const float* __restrict__ hough,
                         float* __restrict__ rois,
                         const float* __restrict__ meta,
                         const float* __restrict__ extents) {
    __shared__ float sv[256];
    __shared__ int   si[256];
    int c   = blockIdx.x;
    int tid = threadIdx.x;

    if (c > 0) {
        float best = -1.0f; int bi = 0;
        #pragma unroll
        for (int k = 0; k < 19; k++) {
            int i = tid + k * 256;
            float v = (i < NB) ? hough[c * NB + i] : -2.0f;
            if (v > best) { best = v; bi = i; }   // ascending i -> first max kept
        }
        sv[tid] = best; si[tid] = bi;
        __syncthreads();
        #pragma unroll
        for (int s = 128; s > 0; s >>= 1) {
            if (tid < s) {
                float v2 = sv[tid + s]; int i2 = si[tid + s];
                if (v2 > sv[tid] || (v2 == sv[tid] && i2 < si[tid])) {
                    sv[tid] = v2; si[tid] = i2;
                }
            }
            __syncthreads();
        }
    }

    if (tid == 0) {
        int peak; float votes;
        if (c == 0) { peak = 0; votes = 0.0f; }   // class-0 hough row is identically 0
        else        { peak = si[0]; votes = sv[0]; }
        float ds    = (c > 0) ? g_dsum[(c - 1) * NB + peak] : 0.0f;
        float depth = ds / fmaxf(votes, 1.0f);
        float cx = 4.0f + 8.0f * (float)(peak % BWID);
        float cy = 4.0f + 8.0f * (float)(peak / BWID);
        float cnt = (float)g_cnt[c];
        float score = votes / fmaxf(cnt, 1.0f);
        bool  valid = (cnt > 5.0f) && (score > 0.3f);
        float fx = meta[0], fy = meta[4];
        float e0 = extents[c*3+0], e1 = extents[c*3+1], e2 = extents[c*3+2];
        float diag = sqrtf(e0*e0 + e1*e1 + e2*e2);
        float sz = fmaxf(fabsf(depth), 0.001f);
        float bw = fabsf(diag * fx) / sz;
        float bh = fabsf(diag * fy) / sz;
        rois[c*6+0] = (float)c;
        rois[c*6+1] = cx - bw * 0.5f;
        rois[c*6+2] = cy - bh * 0.5f;
        rois[c*6+3] = cx + bw * 0.5f;
        rois[c*6+4] = cy + bh * 0.5f;
        rois[c*6+5] = valid ? score : 0.0f;
    }
}

extern "C" void kernel_launch(void* const* d_in, const int* in_sizes, int n_in,
                              void* d_out, int out_size) {
    const int*   label = (const int*)  d_in[0];
    const float* vert  = (const float*)d_in[1];
    const float* meta  = (const float*)d_in[2];
    const float* ext   = (const float*)d_in[3];
    float* out = (float*)d_out;

    // Output is the flattened tuple (rois[3,6], hough[3,4800]) -> 18 + 14400.
    float *rois_p, *hough_p;
    if (out_size >= NC*6 + NC*NB) {
        rois_p = out; hough_p = out + NC*6;
    } else if (out_size >= NC*NB) {
        void* tmp = nullptr;
        cudaGetSymbolAddress(&tmp, g_rois_scratch);
        rois_p = (float*)tmp; hough_p = out;
    } else {
        void* tmp = nullptr;
        cudaGetSymbolAddress(&tmp, g_hough_scratch);
        rois_p = out; hough_p = (float*)tmp;
    }

    zero_small_k<<<1, 32>>>();
    prep_k<<<(PREP_TH + 255) / 256, 256>>>(label, vert, hough_p);
    dim3 vgrid(BGRID, PSPLIT);
    vote_k<<<vgrid, 256>>>(hough_p);
    finish_k<<<NC, 256>>>(hough_p, rois_p, meta, ext);
}

// round 8
// speedup vs baseline: 1.2039x; 1.0082x over previous
#include <cuda_runtime.h>

#define HH 480
#define WW 640
#define NC 3
#define SKIP 5
#define PH 96            // HH/SKIP
#define PW 128           // WW/SKIP
#define NP (PH*PW)       // 12288 sampled pixels
#define BH 60            // bin rows   (GRID=8, start 4)
#define BWID 80          // bin cols
#define NB (BH*BWID)     // 4800 bins
#define BPT 4            // bins per thread (same bin row)  -- proven config
#define CPG (BWID/BPT)   // 20 col-groups per bin row
#define NTH (BH*CPG)     // 1200 worker threads (bin side)
#define BGRID 5          // 5*256 = 1280 threads >= 1200
#define PSPLIT 118       // pixel-slice CTAs -> 5*118 = 590 CTAs (~4/SM)

// ---------- device scratch (zero-initialized at module load) ----------
__device__ float4 g_pix[2*NP]; // {px, py, 2ux, 2uy}
__device__ float  g_dd[2*NP];  // dist
__device__ int    g_n[2];      // compacted counts (class 1,2)  -- reset by finish_k
__device__ int    g_cnt[NC];   // raw label counts (incl. cls0) -- reset by finish_k
__device__ float  g_dsum[2*NB];
__device__ float  g_rois_scratch[NC*6];
__device__ float  g_hough_scratch[NC*NB];

// ---------- kernel 1: zero hough/dsum + gather/compact/prune sampled pixels ----------
#define PREP_TH (NC*NB)   // 14400 >= NP
__global__ void prep_k(const int* __restrict__ label,
                       const float* __restrict__ vert,
                       float* __restrict__ hough) {
    int i = blockIdx.x * blockDim.x + threadIdx.x;
    if (i < NC*NB) hough[i] = 0.0f;
    if (i < 2*NB)  g_dsum[i] = 0.0f;

    if (i >= NP) return;
    int r = i / PW, c = i % PW;
    int vy = r * SKIP, vx = c * SKIP;
    int vl = label[vy * WW + vx];
    atomicAdd(&g_cnt[vl], 1);
    if (vl > 0) {
        int base = (vl * 3) * (HH * WW) + vy * WW + vx;
        float ux = vert[base];
        float uy = vert[base + HH * WW];
        // prune: cos = (d.u)/|d| <= |u|; if ux^2+uy^2 <= 0.25, cos>0.5 impossible.
        if (fmaf(ux, ux, uy * uy) > 0.25f) {
            int seg  = vl - 1;
            int slot = atomicAdd(&g_n[seg], 1) + seg * NP;
            g_pix[slot] = make_float4((float)vx, (float)vy, 2.0f * ux, 2.0f * uy);
            g_dd[slot]  = vert[base + 2 * HH * WW];
        }
    }
}

// ---------- kernel 2: pairwise voting (R7 mainloop verbatim, occ 4) ----------
__global__ void __launch_bounds__(256, 4)
vote_k(float* __restrict__ hough) {
    __shared__ float4 s_pix[256];
    __shared__ float  s_dd[256];

    int tid = threadIdx.x;
    int gt  = blockIdx.x * 256 + tid;
    bool active = gt < NTH;
    int binrow = gt / CPG;
    int colg   = gt % CPG;
    float byf  = 4.0f + 8.0f * (float)binrow;
    float bx0  = 4.0f + 8.0f * (float)(colg * BPT);

    for (int seg = 0; seg < 2; seg++) {
        int n     = g_n[seg];
        int chunk = (n + PSPLIT - 1) / PSPLIT;
        int start = blockIdx.y * chunk;
        int end   = min(start + chunk, n);

        float aH[BPT] = {0.f, 0.f, 0.f, 0.f};
        float aD[BPT] = {0.f, 0.f, 0.f, 0.f};

        for (int t = start; t < end; t += 256) {
            int m = min(256, end - t);
            __syncthreads();
            if (tid < m) {
                int s = seg * NP + t + tid;
                s_pix[tid] = g_pix[s];
                s_dd[tid]  = g_dd[s];
            }
            __syncthreads();

            #pragma unroll 4
            for (int j = 0; j < m; j++) {
                float4 P = s_pix[j];                 // one LDS.128 (broadcast)
                float dd = s_dd[j];
                float px = P.x, py = P.y, ux = P.z, uy = P.w;
                float ddy = byf - py;
                float t2  = fmaf(ddy, ddy, 1e-6f);   // ddy^2 + eps
                float dyu = ddy * uy;                // ddy * 2uy
                #pragma unroll
                for (int b = 0; b < BPT; b++) {
                    float ddx = (bx0 + 8.0f * (float)b) - px;
                    float nxy = fmaf(ddx, ddx, t2);   // ddx^2+ddy^2+eps
                    float dot = fmaf(ddx, ux, dyu);   // 2*(ddx*ux+ddy*uy)
                    bool  ok  = (dot > 0.0f) && (dot * dot > nxy);
                    aH[b] += ok ? 1.0f : 0.0f;
                    aD[b] += ok ? dd   : 0.0f;
                }
            }
        }

        if (active) {
            int binbase = binrow * BWID + colg * BPT;
            #pragma unroll
            for (int b = 0; b < BPT; b++) {
                if (aH[b] != 0.0f) {
                    atomicAdd(&hough[(seg + 1) * NB + binbase + b], aH[b]);
                    atomicAdd(&g_dsum[seg * NB + binbase + b], aD[b]);
                }
            }
        }
        __syncthreads();
    }
}

// ---------- kernel 3: argmax + ROI epilogue (3 CTAs) + counter reset ----------
__global__ void finish_k(const float* __restrict__ hough,
                         float* __restrict__ rois,
                         const float* __restrict__ meta,
                         const float* __restrict__ extents) {
    __shared__ float sv[256];
    __shared__ int   si[256];
    int c   = blockIdx.x;
    int tid = threadIdx.x;

    if (c > 0) {
        float best = -1.0f; int bi = 0;
        #pragma unroll
        for (int k = 0; k < 19; k++) {
            int i = tid + k * 256;
            float v = (i < NB) ? hough[c * NB + i] : -2.0f;
            if (v > best) { best = v; bi = i; }   // ascending i -> first max kept
        }
        sv[tid] = best; si[tid] = bi;
        __syncthreads();
        #pragma unroll
        for (int s = 128; s > 0; s >>= 1) {
            if (tid < s) {
                float v2 = sv[tid + s]; int i2 = si[tid + s];
                if (v2 > sv[tid] || (v2 == sv[tid] && i2 < si[tid])) {
                    sv[tid] = v2; si[tid] = i2;
                }
            }
            __syncthreads();
        }
    }

    if (tid == 0) {
        int peak; float votes;
        if (c == 0) { peak = 0; votes = 0.0f; }   // class-0 hough row is identically 0
        else        { peak = si[0]; votes = sv[0]; }
        float ds    = (c > 0) ? g_dsum[(c - 1) * NB + peak] : 0.0f;
        float depth = ds / fmaxf(votes, 1.0f);
        float cx = 4.0f + 8.0f * (float)(peak % BWID);
        float cy = 4.0f + 8.0f * (float)(peak / BWID);
        float cnt = (float)g_cnt[c];
        float score = votes / fmaxf(cnt, 1.0f);
        bool  valid = (cnt > 5.0f) && (score > 0.3f);
        float fx = meta[0], fy = meta[4];
        float e0 = extents[c*3+0], e1 = extents[c*3+1], e2 = extents[c*3+2];
        float diag = sqrtf(e0*e0 + e1*e1 + e2*e2);
        float sz = fmaxf(fabsf(depth), 0.001f);
        float bw = fabsf(diag * fx) / sz;
        float bh = fabsf(diag * fy) / sz;
        rois[c*6+0] = (float)c;
        rois[c*6+1] = cx - bw * 0.5f;
        rois[c*6+2] = cy - bh * 0.5f;
        rois[c*6+3] = cx + bw * 0.5f;
        rois[c*6+4] = cy + bh * 0.5f;
        rois[c*6+5] = valid ? score : 0.0f;

        // reset counters for the next graph replay (this kernel is last in the
        // graph; stream order puts these writes before next replay's prep_k)
        g_cnt[c] = 0;
        if (c == 0) { g_n[0] = 0; g_n[1] = 0; }
    }
}

extern "C" void kernel_launch(void* const* d_in, const int* in_sizes, int n_in,
                              void* d_out, int out_size) {
    const int*   label = (const int*)  d_in[0];
    const float* vert  = (const float*)d_in[1];
    const float* meta  = (const float*)d_in[2];
    const float* ext   = (const float*)d_in[3];
    float* out = (float*)d_out;

    // Output is the flattened tuple (rois[3,6], hough[3,4800]) -> 18 + 14400.
    float *rois_p, *hough_p;
    if (out_size >= NC*6 + NC*NB) {
        rois_p = out; hough_p = out + NC*6;
    } else if (out_size >= NC*NB) {
        void* tmp = nullptr;
        cudaGetSymbolAddress(&tmp, g_rois_scratch);
        rois_p = (float*)tmp; hough_p = out;
    } else {
        void* tmp = nullptr;
        cudaGetSymbolAddress(&tmp, g_hough_scratch);
        rois_p = out; hough_p = (float*)tmp;
    }

    prep_k<<<(PREP_TH + 255) / 256, 256>>>(label, vert, hough_p);
    dim3 vgrid(BGRID, PSPLIT);
    vote_k<<<vgrid, 256>>>(hough_p);
    finish_k<<<NC, 256>>>(hough_p, rois_p, meta, ext);
}

// round 9
// speedup vs baseline: 1.2772x; 1.0609x over previous
#include <cuda_runtime.h>

#define HH 480
#define WW 640
#define NC 3
#define SKIP 5
#define PH 96            // HH/SKIP
#define PW 128           // WW/SKIP
#define NP (PH*PW)       // 12288 sampled pixels
#define BH 60            // bin rows   (GRID=8, start 4)
#define BWID 80          // bin cols
#define NB (BH*BWID)     // 4800 bins
#define BPT 4            // bins per thread (same bin row)  -- proven config
#define CPG (BWID/BPT)   // 20 col-groups per bin row
#define NTH (BH*CPG)     // 1200 worker threads (bin side)
#define BGRID 5          // 5*256 = 1280 threads >= 1200
#define PSPLIT 118       // pixel-slice CTAs -> 5*118 = 590 CTAs (~4/SM)

// ---------- device scratch (zero-initialized at module load) ----------
__device__ float4 g_pix[2*NP]; // {px, py, 2ux, 2uy}
__device__ float  g_dd[2*NP];  // dist
__device__ int    g_n[2];      // compacted counts (class 1,2)  -- reset by finish_k
__device__ int    g_cnt[NC];   // raw label counts (incl. cls0) -- reset by finish_k
__device__ float  g_dsum[2*NB];
__device__ float  g_rois_scratch[NC*6];
__device__ float  g_hough_scratch[NC*NB];

// ---------- kernel 1: zero hough/dsum + gather/compact/prune (warp-aggregated) ----------
#define PREP_TH (NC*NB)   // 14400 >= NP
__global__ void prep_k(const int* __restrict__ label,
                       const float* __restrict__ vert,
                       float* __restrict__ hough) {
    int i = blockIdx.x * blockDim.x + threadIdx.x;
    if (i < NC*NB) hough[i] = 0.0f;
    if (i < 2*NB)  g_dsum[i] = 0.0f;

    if (i >= NP) return;   // NP % 256 == 0: warps below are fully active
    int lane = threadIdx.x & 31;
    unsigned lmlt = (1u << lane) - 1u;

    int r = i / PW, c = i % PW;
    int vy = r * SKIP, vx = c * SKIP;
    int vl = label[vy * WW + vx];

    // ---- warp-aggregated g_cnt: 3 atomics per warp instead of 32 ----
    #pragma unroll
    for (int cl = 0; cl < NC; cl++) {
        unsigned m = __ballot_sync(0xffffffffu, vl == cl);
        if (m && lane == (__ffs(m) - 1))
            atomicAdd(&g_cnt[cl], __popc(m));
    }

    // ---- gather + prune ----
    float ux = 0.f, uy = 0.f, dd = 0.f;
    bool want = false;
    if (vl > 0) {
        int base = (vl * 3) * (HH * WW) + vy * WW + vx;
        ux = vert[base];
        uy = vert[base + HH * WW];
        dd = vert[base + 2 * HH * WW];
        // prune: cos = (d.u)/|d| <= |u|; if ux^2+uy^2 <= 0.25, cos>0.5 impossible.
        want = fmaf(ux, ux, uy * uy) > 0.25f;
    }

    // ---- warp-aggregated slot allocation: 1 atomic per warp per segment ----
    #pragma unroll
    for (int seg = 0; seg < 2; seg++) {
        bool p = want && (vl == seg + 1);
        unsigned m = __ballot_sync(0xffffffffu, p);
        if (m) {
            int leader = __ffs(m) - 1;
            int base = 0;
            if (lane == leader) base = atomicAdd(&g_n[seg], __popc(m));
            base = __shfl_sync(0xffffffffu, base, leader);
            if (p) {
                int slot = seg * NP + base + __popc(m & lmlt);
                g_pix[slot] = make_float4((float)vx, (float)vy, 2.0f * ux, 2.0f * uy);
                g_dd[slot]  = dd;
            }
        }
    }
}

// ---------- kernel 2: pairwise voting (R7/R8 mainloop verbatim, occ 4) ----------
__global__ void __launch_bounds__(256, 4)
vote_k(float* __restrict__ hough) {
    __shared__ float4 s_pix[256];
    __shared__ float  s_dd[256];

    int tid = threadIdx.x;
    int gt  = blockIdx.x * 256 + tid;
    bool active = gt < NTH;
    int binrow = gt / CPG;
    int colg   = gt % CPG;
    float byf  = 4.0f + 8.0f * (float)binrow;
    float bx0  = 4.0f + 8.0f * (float)(colg * BPT);

    for (int seg = 0; seg < 2; seg++) {
        int n     = g_n[seg];
        int chunk = (n + PSPLIT - 1) / PSPLIT;
        int start = blockIdx.y * chunk;
        int end   = min(start + chunk, n);

        float aH[BPT] = {0.f, 0.f, 0.f, 0.f};
        float aD[BPT] = {0.f, 0.f, 0.f, 0.f};

        for (int t = start; t < end; t += 256) {
            int m = min(256, end - t);
            __syncthreads();
            if (tid < m) {
                int s = seg * NP + t + tid;
                s_pix[tid] = g_pix[s];
                s_dd[tid]  = g_dd[s];
            }
            __syncthreads();

            #pragma unroll 4
            for (int j = 0; j < m; j++) {
                float4 P = s_pix[j];                 // one LDS.128 (broadcast)
                float dd = s_dd[j];
                float px = P.x, py = P.y, ux = P.z, uy = P.w;
                float ddy = byf - py;
                float t2  = fmaf(ddy, ddy, 1e-6f);   // ddy^2 + eps
                float dyu = ddy * uy;                // ddy * 2uy
                #pragma unroll
                for (int b = 0; b < BPT; b++) {
                    float ddx = (bx0 + 8.0f * (float)b) - px;
                    float nxy = fmaf(ddx, ddx, t2);   // ddx^2+ddy^2+eps
                    float dot = fmaf(ddx, ux, dyu);   // 2*(ddx*ux+ddy*uy)
                    bool  ok  = (dot > 0.0f) && (dot * dot > nxy);
                    aH[b] += ok ? 1.0f : 0.0f;
                    aD[b] += ok ? dd   : 0.0f;
                }
            }
        }

        if (active) {
            int binbase = binrow * BWID + colg * BPT;
            #pragma unroll
            for (int b = 0; b < BPT; b++) {
                if (aH[b] != 0.0f) {
                    atomicAdd(&hough[(seg + 1) * NB + binbase + b], aH[b]);
                    atomicAdd(&g_dsum[seg * NB + binbase + b], aD[b]);
                }
            }
        }
        __syncthreads();
    }
}

// ---------- kernel 3: argmax + ROI epilogue (3 CTAs) + counter reset ----------
__global__ void finish_k(const float* __restrict__ hough,
                         float* __restrict__ rois,
                         const float* __restrict__ meta,
                         const float* __restrict__ extents) {
    __shared__ float sv[256];
    __shared__ int   si[256];
    int c   = blockIdx.x;
    int tid = threadIdx.x;

    if (c > 0) {
        float best = -1.0f; int bi = 0;
        #pragma unroll
        for (int k = 0; k < 19; k++) {
            int i = tid + k * 256;
            float v = (i < NB) ? hough[c * NB + i] : -2.0f;
            if (v > best) { best = v; bi = i; }   // ascending i -> first max kept
        }
        sv[tid] = best; si[tid] = bi;
        __syncthreads();
        #pragma unroll
        for (int s = 128; s > 0; s >>= 1) {
            if (tid < s) {
                float v2 = sv[tid + s]; int i2 = si[tid + s];
                if (v2 > sv[tid] || (v2 == sv[tid] && i2 < si[tid])) {
                    sv[tid] = v2; si[tid] = i2;
                }
            }
            __syncthreads();
        }
    }

    if (tid == 0) {
        int peak; float votes;
        if (c == 0) { peak = 0; votes = 0.0f; }   // class-0 hough row is identically 0
        else        { peak = si[0]; votes = sv[0]; }
        float ds    = (c > 0) ? g_dsum[(c - 1) * NB + peak] : 0.0f;
        float depth = ds / fmaxf(votes, 1.0f);
        float cx = 4.0f + 8.0f * (float)(peak % BWID);
        float cy = 4.0f + 8.0f * (float)(peak / BWID);
        float cnt = (float)g_cnt[c];
        float score = votes / fmaxf(cnt, 1.0f);
        bool  valid = (cnt > 5.0f) && (score > 0.3f);
        float fx = meta[0], fy = meta[4];
        float e0 = extents[c*3+0], e1 = extents[c*3+1], e2 = extents[c*3+2];
        float diag = sqrtf(e0*e0 + e1*e1 + e2*e2);
        float sz = fmaxf(fabsf(depth), 0.001f);
        float bw = fabsf(diag * fx) / sz;
        float bh = fabsf(diag * fy) / sz;
        rois[c*6+0] = (float)c;
        rois[c*6+1] = cx - bw * 0.5f;
        rois[c*6+2] = cy - bh * 0.5f;
        rois[c*6+3] = cx + bw * 0.5f;
        rois[c*6+4] = cy + bh * 0.5f;
        rois[c*6+5] = valid ? score : 0.0f;

        // reset counters for the next graph replay
        g_cnt[c] = 0;
        if (c == 0) { g_n[0] = 0; g_n[1] = 0; }
    }
}

extern "C" void kernel_launch(void* const* d_in, const int* in_sizes, int n_in,
                              void* d_out, int out_size) {
    const int*   label = (const int*)  d_in[0];
    const float* vert  = (const float*)d_in[1];
    const float* meta  = (const float*)d_in[2];
    const float* ext   = (const float*)d_in[3];
    float* out = (float*)d_out;

    // Output is the flattened tuple (rois[3,6], hough[3,4800]) -> 18 + 14400.
    float *rois_p, *hough_p;
    if (out_size >= NC*6 + NC*NB) {
        rois_p = out; hough_p = out + NC*6;
    } else if (out_size >= NC*NB) {
        void* tmp = nullptr;
        cudaGetSymbolAddress(&tmp, g_rois_scratch);
        rois_p = (float*)tmp; hough_p = out;
    } else {
        void* tmp = nullptr;
        cudaGetSymbolAddress(&tmp, g_hough_scratch);
        rois_p = out; hough_p = (float*)tmp;
    }

    prep_k<<<(PREP_TH + 255) / 256, 256>>>(label, vert, hough_p);
    dim3 vgrid(BGRID, PSPLIT);
    vote_k<<<vgrid, 256>>>(hough_p);
    finish_k<<<NC, 256>>>(hough_p, rois_p, meta, ext);
}